// round 11
// baseline (speedup 1.0000x reference)
#include <cuda_runtime.h>
#include <math.h>
#include <stdint.h>

#define NN 4096
#define CAP 512
#define CAPG (CAP / 2)

// ---------------- device globals (allocation-free scratch) ----------------
__device__ __align__(16) signed char g_B8[(size_t)NN * NN];   // B = m + m^T
__device__ __align__(16) signed char g_d8[NN];
__device__ int g_nD;
__device__ __align__(16) uint2 g_list2[(size_t)NN * CAPG];    // 2 entries per uint2
__device__ int g_cnt[NN];
__device__ int g_rowsE[NN], g_colEf[NN];
__device__ unsigned long long g_triS, g_triE;
__device__ unsigned long long g_T1, g_T2, g_S, g_TA, g_TB;
__device__ unsigned g_done;

// Fused: mod_adj + B = m + m^T + diag + zeroing of accumulators.
// hard = 1 <=> logit(p)+logit(u) > 0 <=> p + (u-1) > 0 (u-1 exact by Sterbenz).
__global__ void k_fuse(const float* __restrict__ ori, const float* __restrict__ cp,
                       const float* __restrict__ u, float* __restrict__ mod) {
    __shared__ unsigned m1w[32][9];
    __shared__ unsigned m2w[32][9];
    const int bx = blockIdx.x, by = blockIdx.y;
    if (bx < by) return;
    const int bi = by * 32, bj = bx * 32;
    const int tx = threadIdx.x;   // 0..7
    const int ty = threadIdx.y;   // 0..31
    const int tid = ty * 8 + tx;
    const bool diag = (bx == by);

    if (diag && tid < 32) g_colEf[bi + tid] = 0;
    if (bx == 0 && by == 0 && tid == 0) {
        g_triS = 0ull; g_triE = 0ull; g_nD = 0; g_done = 0u;
        g_T1 = 0ull; g_T2 = 0ull; g_S = 0ull; g_TA = 0ull; g_TB = 0ull;
    }

    {
        size_t idx = ((size_t)(bi + ty) * NN + bj + tx * 4) >> 2;
        float4 o = __ldcs((const float4*)ori + idx);
        float4 c = __ldcs((const float4*)cp + idx);
        float4 w = __ldcs((const float4*)u + idx);
        float4 m;
        m.x = (c.x + (w.x - 1.0f) > 0.0f) ? -o.x : o.x;
        m.y = (c.y + (w.y - 1.0f) > 0.0f) ? -o.y : o.y;
        m.z = (c.z + (w.z - 1.0f) > 0.0f) ? -o.z : o.z;
        m.w = (c.w + (w.w - 1.0f) > 0.0f) ? -o.w : o.w;
        __stcs((float4*)mod + idx, m);
        m1w[ty][tx] = ((unsigned)(int)m.x & 0xFFu)
                    | (((unsigned)(int)m.y & 0xFFu) << 8)
                    | (((unsigned)(int)m.z & 0xFFu) << 16)
                    | (((unsigned)(int)m.w & 0xFFu) << 24);
    }
    if (!diag) {
        size_t idx = ((size_t)(bj + ty) * NN + bi + tx * 4) >> 2;
        float4 o = __ldcs((const float4*)ori + idx);
        float4 c = __ldcs((const float4*)cp + idx);
        float4 w = __ldcs((const float4*)u + idx);
        float4 m;
        m.x = (c.x + (w.x - 1.0f) > 0.0f) ? -o.x : o.x;
        m.y = (c.y + (w.y - 1.0f) > 0.0f) ? -o.y : o.y;
        m.z = (c.z + (w.z - 1.0f) > 0.0f) ? -o.z : o.z;
        m.w = (c.w + (w.w - 1.0f) > 0.0f) ? -o.w : o.w;
        __stcs((float4*)mod + idx, m);
        m2w[ty][tx] = ((unsigned)(int)m.x & 0xFFu)
                    | (((unsigned)(int)m.y & 0xFFu) << 8)
                    | (((unsigned)(int)m.z & 0xFFu) << 16)
                    | (((unsigned)(int)m.w & 0xFFu) << 24);
    }
    __syncthreads();
    {   // B tile1: rows bi+ty, cols bj+tx*4..+3
        unsigned w1 = m1w[ty][tx];
        unsigned out = 0;
        #pragma unroll
        for (int q = 0; q < 4; q++) {
            int a = (int)(w1 << (24 - 8 * q)) >> 24;
            unsigned wt = diag ? m1w[tx * 4 + q][ty >> 2] : m2w[tx * 4 + q][ty >> 2];
            int b = (int)(wt << (24 - 8 * (ty & 3))) >> 24;
            out |= ((unsigned)(a + b) & 0xFFu) << (8 * q);
        }
        *(unsigned*)(g_B8 + (size_t)(bi + ty) * NN + bj + tx * 4) = out;
    }
    if (!diag) {  // B tile2: rows bj+ty, cols bi+tx*4..+3
        unsigned w1 = m2w[ty][tx];
        unsigned out = 0;
        #pragma unroll
        for (int q = 0; q < 4; q++) {
            int a = (int)(w1 << (24 - 8 * q)) >> 24;
            unsigned wt = m1w[tx * 4 + q][ty >> 2];
            int b = (int)(wt << (24 - 8 * (ty & 3))) >> 24;
            out |= ((unsigned)(a + b) & 0xFFu) << (8 * q);
        }
        *(unsigned*)(g_B8 + (size_t)(bj + ty) * NN + bi + tx * 4) = out;
    }
    if (diag && tx == (ty >> 2)) {
        int d = (int)(m1w[ty][tx] << (24 - 8 * (ty & 3))) >> 24;
        g_d8[bi + ty] = (signed char)d;
    }
}

// Per-row: full nnz lists (packed 2/uint2), row sums, colEf atomics, scalar-term atomics.
// List entry (row r, col c): idx=c, b=B[r,c], e=E[c,r] (with d_r).
__global__ void __launch_bounds__(256) k_lists() {
    __shared__ unsigned s_ent[CAP];
    __shared__ int scnt;
    __shared__ int wsum[24];
    const int r = blockIdx.x, tid = threadIdx.x, lane = tid & 31, wid = tid >> 5;
    if (tid == 0) scnt = 0;
    __syncthreads();
    const int dr = (int)g_d8[r];

    uint4 bw4 = __ldcs((const uint4*)(g_B8 + (size_t)r * NN) + tid);
    uint4 dw4 = *(const uint4*)(g_d8 + tid * 16);
    unsigned bw[4] = {bw4.x, bw4.y, bw4.z, bw4.w};
    unsigned dw[4] = {dw4.x, dw4.y, dw4.z, dw4.w};

    int sB = 0, sBd = 0, sE = 0, nzc = 0;
    unsigned nzm[4], ew[4];
    #pragma unroll
    for (int q = 0; q < 4; q++) {
        unsigned b = bw[q], d = dw[q];
        sB  = __dp4a((int)b, 0x01010101, sB);
        sBd = __dp4a((int)b, (int)d, sBd);
        unsigned e;
        if (d == 0u) {
            e = (unsigned)__vabsss4((int)b);
        } else {
            e = 0;
            #pragma unroll
            for (int t = 0; t < 4; t++) {
                int bt = (int)(b << (24 - 8 * t)) >> 24;
                int dt = (int)(d << (24 - 8 * t)) >> 24;
                int et = dt ? (abs(bt - dt) - 1) : abs(bt);
                e |= ((unsigned)et & 0xFFu) << (8 * t);
            }
        }
        ew[q] = e;
        sE = __dp4a((int)e, 0x01010101, sE);
        nzm[q] = ~__vcmpeq4(b, 0u);
        nzc += __popc(nzm[q]) >> 3;
    }
    // colEf: rows r in D add E[r,c] (E-support subset of B-support)
    if (dr != 0) {
        #pragma unroll
        for (int q = 0; q < 4; q++) {
            unsigned mk = nzm[q];
            while (mk) {
                int bit = __ffs(mk) - 1;
                int t = bit >> 3;
                mk &= ~(0xFFu << (t * 8));
                int et = (int)(ew[q] << (24 - 8 * t)) >> 24;
                if (et) atomicAdd(&g_colEf[tid * 16 + q * 4 + t], et);
            }
        }
    }
    // extraction into staging (order-free)
    int pos = 0;
    if (nzc) pos = atomicAdd(&scnt, nzc);
    #pragma unroll
    for (int q = 0; q < 4; q++) {
        unsigned mk = nzm[q];
        while (mk) {
            int bit = __ffs(mk) - 1;
            int t = bit >> 3;
            mk &= ~(0xFFu << (t * 8));
            int bt = (int)(bw[q] << (24 - 8 * t)) >> 24;
            int ec = dr ? (abs(bt - dr) - 1) : abs(bt);
            if (pos < CAP)
                s_ent[pos] = (unsigned)(tid * 16 + q * 4 + t)
                           | (((unsigned)bt & 0xFFu) << 16)
                           | (((unsigned)ec & 0xFFu) << 24);
            pos++;
        }
    }
    // row-sum reductions
    #pragma unroll
    for (int o = 16; o > 0; o >>= 1) {
        sB  += __shfl_down_sync(0xFFFFFFFFu, sB, o);
        sBd += __shfl_down_sync(0xFFFFFFFFu, sBd, o);
        sE  += __shfl_down_sync(0xFFFFFFFFu, sE, o);
    }
    if (lane == 0) { wsum[wid] = sB; wsum[8 + wid] = sBd; wsum[16 + wid] = sE; }
    __syncthreads();
    if (tid == 0) {
        int a = 0, c = 0, d = 0;
        #pragma unroll
        for (int w = 0; w < 8; w++) { a += wsum[w]; c += wsum[8 + w]; d += wsum[16 + w]; }
        g_rowsE[r] = d;
        // fold scalar reduction terms (order-free modular int64 atomics)
        atomicAdd(&g_T1, (unsigned long long)((long long)c * (long long)a));
        if (dr != 0) {
            atomicAdd(&g_T2, (unsigned long long)((long long)dr * (long long)a));
            atomicAdd(&g_S, (unsigned long long)(long long)dr);
            atomicAdd(&g_TB, (unsigned long long)(long long)d);
            atomicAdd(&g_nD, 1);
        }
    }
    int cnt = min(scnt, CAP);
    if (tid == 0) g_cnt[r] = cnt;
    int cnt4 = (cnt + 3) & ~3;
    for (int t = cnt + tid; t < cnt4; t += 256) s_ent[t] = 0;
    __syncthreads();
    int ng = cnt4 >> 1;
    for (int g = tid; g < ng; g += 256) {
        unsigned e0 = s_ent[2 * g], e1 = s_ent[2 * g + 1];
        unsigned x = (e0 & 0xFFFFu) | ((e1 & 0xFFFFu) << 16);
        unsigned y = __byte_perm(e0 >> 16, e1 >> 16, 0x5410);
        g_list2[(size_t)r * CAPG + g] = make_uint2(x, y);
    }
}

// Sparse traces: triS = tr(B^3), triE = tr(E^3); folds TA and the final balance
// (last finishing block computes the output — threadfence-reduction pattern).
__global__ void __launch_bounds__(256) k_tri(float* __restrict__ out, int out_size) {
    __shared__ unsigned short s_be[NN];   // (B[j,i], E[j,i]) packed bytes — 8 KB
    __shared__ uint2 jl[CAPG];
    __shared__ long long redS[8], redE[8];
    const int j = blockIdx.x, tid = threadIdx.x, lane = tid & 31, wid = tid >> 5;

    // zero s_be (8 KB) and load own list
    ((int4*)s_be)[tid] = make_int4(0, 0, 0, 0);
    ((int4*)s_be)[tid + 256] = make_int4(0, 0, 0, 0);
    const int cj = g_cnt[j];
    const int njg = ((cj + 3) & ~3) >> 1;
    for (int t = tid; t < njg; t += 256) jl[t] = g_list2[(size_t)j * CAPG + t];
    __syncthreads();

    // scatter: s_be[i] = (B[j,i], E[j,i]) with E[j,i] = f(B[j,i], d_i)
    for (int t = tid; t < cj; t += 256) {
        uint2 w = jl[t >> 1];
        int hi = t & 1;
        int i = hi ? (int)(w.x >> 16) : (int)(w.x & 0xFFFFu);
        int b = hi ? ((int)(w.y << 8) >> 24) : ((int)(w.y << 24) >> 24);
        int di = (int)g_d8[i];
        int e = di ? (abs(b - di) - 1) : abs(b);
        s_be[i] = (unsigned short)(((unsigned)b & 0xFFu) | (((unsigned)e & 0xFFu) << 8));
    }
    __syncthreads();

    int aS = 0, aE = 0;
    for (int kk = wid; kk < cj; kk += 8) {
        uint2 w = jl[kk >> 1];
        int hi = kk & 1;
        int k = hi ? (int)(w.x >> 16) : (int)(w.x & 0xFFFFu);
        int bkj = hi ? ((int)(w.y << 8) >> 24) : ((int)(w.y << 24) >> 24);
        int ekj = hi ? ((int)w.y >> 24)        : ((int)(w.y << 16) >> 24);
        const uint4* lk = (const uint4*)(g_list2 + (size_t)k * CAPG);
        int ck4 = (__ldg(&g_cnt[k]) + 3) >> 2;
        int sk = 0, ek = 0;
        for (int t = lane; t < ck4; t += 32) {
            uint4 w4 = __ldg(&lk[t]);
            {
                int i0 = (int)(w4.x & 0xFFFFu), i1 = (int)(w4.x >> 16);
                unsigned v0 = s_be[i0];
                unsigned v1 = s_be[i1];
                unsigned be2 = __byte_perm(v0, v1, 0x5410);
                sk = __dp4a((int)(w4.y & 0x00FF00FFu), (int)be2, sk);
                ek = __dp4a((int)(w4.y & 0xFF00FF00u), (int)be2, ek);
            }
            {
                int i0 = (int)(w4.z & 0xFFFFu), i1 = (int)(w4.z >> 16);
                unsigned v0 = s_be[i0];
                unsigned v1 = s_be[i1];
                unsigned be2 = __byte_perm(v0, v1, 0x5410);
                sk = __dp4a((int)(w4.w & 0x00FF00FFu), (int)be2, sk);
                ek = __dp4a((int)(w4.w & 0xFF00FF00u), (int)be2, ek);
            }
        }
        aS += bkj * sk;
        aE += ekj * ek;
    }
    #pragma unroll
    for (int o = 16; o > 0; o >>= 1) {
        aS += __shfl_down_sync(0xFFFFFFFFu, aS, o);
        aE += __shfl_down_sync(0xFFFFFFFFu, aE, o);
    }
    if (lane == 0) { redS[wid] = aS; redE[wid] = aE; }
    __syncthreads();
    if (tid == 0) {
        long long s = 0, t = 0;
        #pragma unroll
        for (int w = 0; w < 8; w++) { s += redS[w]; t += redE[w]; }
        atomicAdd(&g_triS, (unsigned long long)s);
        atomicAdd(&g_triE, (unsigned long long)t);
        atomicAdd(&g_TA, (unsigned long long)((long long)g_colEf[j] * (long long)g_rowsE[j]));
        __threadfence();
        unsigned prev = atomicAdd(&g_done, 1u);
        if (prev == (unsigned)(NN - 1)) {
            // all blocks' atomics are globally visible (each fenced before g_done)
            long long triS = (long long)atomicAdd(&g_triS, 0ull);
            long long triE = (long long)atomicAdd(&g_triE, 0ull);
            long long T1 = (long long)atomicAdd(&g_T1, 0ull);
            long long T2 = (long long)atomicAdd(&g_T2, 0ull);
            long long Sv = (long long)atomicAdd(&g_S, 0ull);
            long long TA = (long long)atomicAdd(&g_TA, 0ull);
            long long TB = (long long)atomicAdd(&g_TB, 0ull);
            long long nD = (long long)atomicAdd(&g_nD, 0);
            // tr(A^3)  = tr(B^3) - 3*T1 + 3*S*T2 - S^3
            // tr(|A|^3)= tr(E^3) + 3*TA + 3*|D|*TB + |D|^3
            long long tr3  = triS - 3 * T1 + 3 * Sv * T2 - Sv * Sv * Sv;
            long long tr3a = triE + 3 * TA + 3 * nD * TB + nD * nD * nD;
            out[out_size - 1] = (float)(0.5 * (1.0 + (double)tr3 / (double)tr3a));
        }
    }
}

// ---------------- launch ----------------
extern "C" void kernel_launch(void* const* d_in, const int* in_sizes, int n_in,
                              void* d_out, int out_size) {
    const float* ori = (const float*)d_in[0];
    const float* cp  = (const float*)d_in[1];
    const float* u   = (const float*)d_in[2];
    float* out = (float*)d_out;

    k_fuse<<<dim3(128, 128), dim3(8, 32)>>>(ori, cp, u, out);
    k_lists<<<NN, 256>>>();
    k_tri<<<NN, 256>>>(out, out_size);
}